// round 7
// baseline (speedup 1.0000x reference)
#include <cuda_runtime.h>
#include <stdint.h>
#include <math.h>

#define FMASK 0xffffffffu

static __device__ __forceinline__ float ex2f(float x){ float y; asm("ex2.approx.f32 %0, %1;" : "=f"(y) : "f"(x)); return y; }
static __device__ __forceinline__ float lg2f(float x){ float y; asm("lg2.approx.f32 %0, %1;" : "=f"(y) : "f"(x)); return y; }
static __device__ __forceinline__ float rcpf(float x){ float y; asm("rcp.approx.f32 %0, %1;" : "=f"(y) : "f"(x)); return y; }
static __device__ __forceinline__ void cp16(uint32_t dst, const void* src){
    asm volatile("cp.async.cg.shared.global [%0], [%1], 16;" :: "r"(dst), "l"(src) : "memory");
}
static __device__ __forceinline__ void cpcommit(){ asm volatile("cp.async.commit_group;" ::: "memory"); }
static __device__ __forceinline__ void cpwait(int n){
    if (n == 0) asm volatile("cp.async.wait_group 0;" ::: "memory");
    else if (n == 1) asm volatile("cp.async.wait_group 1;" ::: "memory");
    else if (n == 2) asm volatile("cp.async.wait_group 2;" ::: "memory");
    else asm volatile("cp.async.wait_group 3;" ::: "memory");
}
static __device__ __forceinline__ void barsync64(int id){ asm volatile("bar.sync %0, 64;" :: "r"(id) : "memory"); }
static __device__ __forceinline__ void bararr64(int id){ asm volatile("bar.arrive %0, 64;" :: "r"(id) : "memory"); }
static __device__ __forceinline__ void membar_cta(){ asm volatile("membar.cta;" ::: "memory"); }

// packed f32x2 helpers
union F2 { unsigned long long u; float f[2]; };
static __device__ __forceinline__ unsigned long long dup2(float x){
    unsigned long long r; asm("mov.b64 %0, {%1, %1};" : "=l"(r) : "f"(x)); return r;
}
static __device__ __forceinline__ unsigned long long pk2(float lo, float hi){
    unsigned long long r; asm("mov.b64 %0, {%1, %2};" : "=l"(r) : "f"(lo), "f"(hi)); return r;
}
static __device__ __forceinline__ unsigned long long fma2(unsigned long long a, unsigned long long b, unsigned long long c){
    unsigned long long d; asm("fma.rn.f32x2 %0, %1, %2, %3;" : "=l"(d) : "l"(a), "l"(b), "l"(c)); return d;
}
static __device__ __forceinline__ unsigned long long add2(unsigned long long a, unsigned long long b){
    unsigned long long d; asm("add.rn.f32x2 %0, %1, %2;" : "=l"(d) : "l"(a), "l"(b)); return d;
}
static __device__ __forceinline__ unsigned long long mul2(unsigned long long a, unsigned long long b){
    unsigned long long d; asm("mul.rn.f32x2 %0, %1, %2;" : "=l"(d) : "l"(a), "l"(b)); return d;
}
static __device__ __forceinline__ float2 unpk2(unsigned long long v){
    float2 f; asm("mov.b64 {%0, %1}, %2;" : "=f"(f.x), "=f"(f.y) : "l"(v)); return f;
}

// Scratch (allocation-free __device__ globals)
__device__ float g_e[128*1024*16];   // unnormalized softmax numerators e_t
__device__ float g_u[128*1024*16];   // raw mixed logits u_t (l_t = u_t * r_{t-1})
__device__ float g_r[128*1024];      // r_t = 1/S_t  (y_t = e_t * r_t)

// ============================================================================
// Kernel 1: scan — 2 warps/CTA: warp0 = recurrence chain, warp1 = memory.
// 32-slot logits ring = 4 groups of 8 steps. Named barriers:
//   READY(h): id 1 + (h&3)   memory -> compute (group h slots landed)
//   DONE(h):  id 5 + (h&3)   compute -> memory (group h slots consumed, wbuf filled)
// ============================================================================
__global__ __launch_bounds__(64, 1)
void scan_kernel(const float* __restrict__ logits,
                 const float* __restrict__ gum)
{
    constexpr int T = 1024;
    constexpr float SCALE = 2.8853900817779268f;   // (1/tau)*log2(e), tau = 0.5

    __shared__ __align__(16) float ring[32*256];   // 32 slots x 1024B
    __shared__ __align__(16) float gring[32*16];
    __shared__ __align__(16) float wbuf[16*40];    // 16 steps x (e16|u16|r|pad)

    const int b = blockIdx.x;
    const int w = threadIdx.x >> 5;
    const int lane = threadIdx.x & 31;

    const float* Lrow = logits + (size_t)b * ((size_t)T * 256);
    const float* grow = gum    + (size_t)b * ((size_t)T * 16);

    if (w == 1) {
        // ---------------- memory warp ----------------
        uint32_t ring_b  = (uint32_t)__cvta_generic_to_shared(ring);
        uint32_t gring_b = (uint32_t)__cvta_generic_to_shared(gring);
        float* pe = g_e + (size_t)b * (T * 16);
        float* pu = g_u + (size_t)b * (T * 16);
        float* pr = g_r + (size_t)b * T;

        // issue groups 0..3 (one commit per group)
        #pragma unroll
        for (int g = 0; g < 4; ++g) {
            #pragma unroll
            for (int sl = 0; sl < 8; ++sl) {
                const int t = g*8 + sl;
                const int st = t & 31;
                uint32_t sb = ring_b + st*1024 + lane*16;
                const float* gp = Lrow + (size_t)t*256 + lane*4;
                cp16(sb, gp);
                cp16(sb + 512, gp + 128);
                if (lane < 4) cp16(gring_b + st*64 + lane*16, grow + (size_t)t*16 + lane*4);
            }
            cpcommit();
        }
        cpwait(3); membar_cta(); bararr64(1 + 0);   // READY(0)
        cpwait(2); membar_cta(); bararr64(1 + 1);   // READY(1)
        cpwait(1); membar_cta(); bararr64(1 + 2);   // READY(2)

        const int sl_a = lane >> 3, q = lane & 7;

        for (int h = 4; h < 128; ++h) {
            const int g = h - 4;
            barsync64(5 + (g & 3));                 // DONE(g)
            // writeback group g (8 steps) from wbuf
            #pragma unroll
            for (int half = 0; half < 2; ++half) {
                const int sl = sl_a + half*4;
                const int t = g*8 + sl;
                const int ws = t & 15;
                const float4 v = *reinterpret_cast<const float4*>(&wbuf[ws*40 + q*4]);
                float* dst = (q < 4) ? (pe + (size_t)t*16 + q*4)
                                     : (pu + (size_t)t*16 + (q-4)*4);
                *reinterpret_cast<float4*>(dst) = v;
            }
            if (lane < 8) {
                const int t = g*8 + lane;
                pr[t] = wbuf[(t & 15)*40 + 32];
            }
            // issue group h
            #pragma unroll
            for (int sl = 0; sl < 8; ++sl) {
                const int t = h*8 + sl;
                const int st = t & 31;
                uint32_t sb = ring_b + st*1024 + lane*16;
                const float* gp = Lrow + (size_t)t*256 + lane*4;
                cp16(sb, gp);
                cp16(sb + 512, gp + 128);
                if (lane < 4) cp16(gring_b + st*64 + lane*16, grow + (size_t)t*16 + lane*4);
            }
            cpcommit();
            cpwait(1); membar_cta();
            bararr64(1 + ((h-1) & 3));              // READY(h-1)
        }
        cpwait(0); membar_cta();
        bararr64(1 + (127 & 3));                    // READY(127)
        // tail writebacks: groups 124..127
        for (int g = 124; g < 128; ++g) {
            barsync64(5 + (g & 3));                 // DONE(g)
            #pragma unroll
            for (int half = 0; half < 2; ++half) {
                const int sl = sl_a + half*4;
                const int t = g*8 + sl;
                const int ws = t & 15;
                const float4 v = *reinterpret_cast<const float4*>(&wbuf[ws*40 + q*4]);
                float* dst = (q < 4) ? (pe + (size_t)t*16 + q*4)
                                     : (pu + (size_t)t*16 + (q-4)*4);
                *reinterpret_cast<float4*>(dst) = v;
            }
            if (lane < 8) {
                const int t = g*8 + lane;
                pr[t] = wbuf[(t & 15)*40 + 32];
            }
        }
    } else {
        // ---------------- compute warp: the recurrence chain ----------------
        const int j = lane & 15;
        const bool wr = (lane < 16);

        barsync64(1 + 0);   // READY(0)

        F2 Lp[8], PA[8], PB[8];
        #pragma unroll
        for (int m = 0; m < 8; ++m) {
            Lp[m].f[0] = ring[(2*m)*16 + j];
            Lp[m].f[1] = ring[(2*m + 1)*16 + j];
            PA[m].f[0] = 1.0f; PA[m].f[1] = 1.0f;
        }
        float gC = gring[j] * SCALE;
        float rC = 0.0625f * SCALE;

#define SUBSTEP(PIN, POUT, TT)                                                           \
        {                                                                                \
            F2 a0, a1, a2, a3, s01, s23, at;                                             \
            a0.u = mul2(PIN[0].u, Lp[0].u);                                              \
            a1.u = mul2(PIN[1].u, Lp[1].u);                                              \
            a2.u = mul2(PIN[2].u, Lp[2].u);                                              \
            a3.u = mul2(PIN[3].u, Lp[3].u);                                              \
            a0.u = fma2(PIN[4].u, Lp[4].u, a0.u);                                        \
            a1.u = fma2(PIN[5].u, Lp[5].u, a1.u);                                        \
            a2.u = fma2(PIN[6].u, Lp[6].u, a2.u);                                        \
            a3.u = fma2(PIN[7].u, Lp[7].u, a3.u);                                        \
            s01.u = add2(a0.u, a1.u);                                                    \
            s23.u = add2(a2.u, a3.u);                                                    \
            at.u  = add2(s01.u, s23.u);                                                  \
            const float x = fmaf(at.f[1], rC, fmaf(at.f[0], rC, gC));                    \
            const float en = ex2f(x);                                                    \
            _Pragma("unroll")                                                            \
            for (int m = 0; m < 8; ++m) {                                                \
                POUT[m].f[0] = __shfl_sync(FMASK, en, 2*m);                              \
                POUT[m].f[1] = __shfl_sync(FMASK, en, 2*m + 1);                          \
            }                                                                            \
            const int ws = (TT) & 15;                                                    \
            if (wr) { wbuf[ws*40 + j] = en;                                              \
                      wbuf[ws*40 + 16 + j] = at.f[0] + at.f[1]; }                        \
            {   const int sn = ((TT) + 1) & 31;                                          \
                const float* rb = ring + sn*256;                                         \
                _Pragma("unroll")                                                        \
                for (int m = 0; m < 8; ++m) {                                            \
                    Lp[m].f[0] = rb[(2*m)*16 + j];                                       \
                    Lp[m].f[1] = rb[(2*m + 1)*16 + j];                                   \
                }                                                                        \
                gC = gring[sn*16 + j] * SCALE;                                           \
            }                                                                            \
            F2 t0, t1, t01, tS;                                                          \
            t0.u  = add2(POUT[0].u, POUT[1].u);                                          \
            t1.u  = add2(POUT[2].u, POUT[3].u);                                          \
            t01.u = add2(t0.u, t1.u);                                                    \
            t0.u  = add2(POUT[4].u, POUT[5].u);                                          \
            t1.u  = add2(POUT[6].u, POUT[7].u);                                          \
            tS.u  = add2(t0.u, t1.u);                                                    \
            tS.u  = add2(t01.u, tS.u);                                                   \
            const float S = tS.f[0] + tS.f[1];                                           \
            const float r = rcpf(S);                                                     \
            rC = r * SCALE;                                                              \
            if (lane == 0) wbuf[ws*40 + 32] = r;                                         \
        }

        for (int h = 0; h < 128; ++h) {
            if (h) { membar_cta(); bararr64(5 + ((h-1) & 3)); }   // DONE(h-1)
            if (h < 127) barsync64(1 + ((h+1) & 3));              // READY(h+1)
            const int t0 = h*8;
            #pragma unroll
            for (int s = 0; s < 8; s += 2) {
                SUBSTEP(PA, PB, t0 + s)
                SUBSTEP(PB, PA, t0 + s + 1)
            }
        }
        membar_cta(); bararr64(5 + (127 & 3));                    // DONE(127)
#undef SUBSTEP
    }
}

// ============================================================================
// Kernel 2: expansion — A_seq = y·A, B_seq = y·Bm. Bandwidth-bound, f32x2 FMA.
// ============================================================================
__global__ __launch_bounds__(384, 1)
void expand_kernel(const float* __restrict__ Amat,
                   const float* __restrict__ Bmat,
                   float* __restrict__ out)
{
    __shared__ __align__(16) float es[64*16];
    __shared__ float rs[64];

    const int b = blockIdx.y;
    const int t0 = blockIdx.x * 64;
    const int tid = threadIdx.x;
    const int tsub = tid / 96;
    const int e96 = tid % 96;

    float* outA = out;                // (B,T,16,16)
    float* outB = out + 33554432u;    // (B,T,16,8)

    unsigned long long M[32];
    const float* Msrc;
    int stride, base;
    if (e96 < 64) { const int i = e96 >> 2, jc = (e96 & 3) * 4; base = i*16 + jc; stride = 256; Msrc = Amat; }
    else          { const int q = e96 - 64; const int i = q >> 1, jc = (q & 1) * 4; base = i*8 + jc; stride = 128; Msrc = Bmat; }
    #pragma unroll
    for (int k = 0; k < 16; ++k) {
        const float4 v = *reinterpret_cast<const float4*>(Msrc + k*stride + base);
        M[2*k]   = pk2(v.x, v.y);
        M[2*k+1] = pk2(v.z, v.w);
    }

    const float* esrc = g_e + ((size_t)b*1024 + t0) * 16;
    if (tid < 256) *reinterpret_cast<float4*>(&es[tid*4]) = *reinterpret_cast<const float4*>(&esrc[tid*4]);
    if (tid >= 320) rs[tid - 320] = g_r[(size_t)b*1024 + t0 + (tid - 320)];
    __syncthreads();

    float* outp = ((e96 < 64) ? outA : outB) + ((size_t)b*1024 + t0) * (size_t)stride + base;

    #pragma unroll 4
    for (int tt = 0; tt < 16; ++tt) {
        const int tl = tt*4 + tsub;
        const float4* ep4 = reinterpret_cast<const float4*>(&es[tl*16]);
        const float4 y0 = ep4[0], y1 = ep4[1], y2 = ep4[2], y3 = ep4[3];
        unsigned long long d[16];
        d[0]=dup2(y0.x); d[1]=dup2(y0.y); d[2]=dup2(y0.z); d[3]=dup2(y0.w);
        d[4]=dup2(y1.x); d[5]=dup2(y1.y); d[6]=dup2(y1.z); d[7]=dup2(y1.w);
        d[8]=dup2(y2.x); d[9]=dup2(y2.y); d[10]=dup2(y2.z); d[11]=dup2(y2.w);
        d[12]=dup2(y3.x); d[13]=dup2(y3.y); d[14]=dup2(y3.z); d[15]=dup2(y3.w);
        unsigned long long a0 = mul2(d[0], M[0]);
        unsigned long long a1 = mul2(d[0], M[1]);
        #pragma unroll
        for (int k = 1; k < 16; ++k) {
            a0 = fma2(d[k], M[2*k],   a0);
            a1 = fma2(d[k], M[2*k+1], a1);
        }
        const unsigned long long rd = dup2(rs[tl]);
        a0 = mul2(a0, rd);
        a1 = mul2(a1, rd);
        const float2 f0 = unpk2(a0), f1 = unpk2(a1);
        *reinterpret_cast<float4*>(outp + (size_t)tl * stride) = make_float4(f0.x, f0.y, f1.x, f1.y);
    }
}

// ============================================================================
// Kernel 3: scalars — lq, lp, C_seq.
// ============================================================================
__global__ __launch_bounds__(128, 1)
void scalars_kernel(const float* __restrict__ transP,
                    const float* __restrict__ Cmat,
                    float* __restrict__ out)
{
    constexpr float LOG2E = 1.4426950408889634f;
    constexpr float LN2   = 0.6931471805599453f;
    __shared__ __align__(16) float lgP[256];

    const int b = blockIdx.y;
    const int tid = threadIdx.x;
    const int t = blockIdx.x * 128 + tid;

    float* outC  = out + 50331648u;   // (B,1,32,16)
    float* outLq = out + 50397184u;   // (B,T)
    float* outLp = out + 50528256u;   // (B,T)

    lgP[tid] = logf(transP[tid]);
    lgP[tid + 128] = logf(transP[tid + 128]);
    if (blockIdx.x == 0) {
        #pragma unroll
        for (int i = tid; i < 512; i += 128) outC[b*512 + i] = Cmat[i];
    }
    __syncthreads();

    const size_t bt = (size_t)b*1024 + t;
    float es[16], us[16], ep[16];
    {
        const float4* e4 = reinterpret_cast<const float4*>(g_e + bt*16);
        const float4* u4 = reinterpret_cast<const float4*>(g_u + bt*16);
        #pragma unroll
        for (int q = 0; q < 4; ++q) {
            const float4 ev = e4[q], uv = u4[q];
            es[q*4+0]=ev.x; es[q*4+1]=ev.y; es[q*4+2]=ev.z; es[q*4+3]=ev.w;
            us[q*4+0]=uv.x; us[q*4+1]=uv.y; us[q*4+2]=uv.z; us[q*4+3]=uv.w;
        }
    }
    const float rt = g_r[bt];
    float rm;
    if (t == 0) {
        rm = 0.0625f;
        #pragma unroll
        for (int k = 0; k < 16; ++k) ep[k] = 1.0f;
    } else {
        rm = g_r[bt - 1];
        const float4* p4 = reinterpret_cast<const float4*>(g_e + (bt - 1)*16);
        #pragma unroll
        for (int q = 0; q < 4; ++q) {
            const float4 pv = p4[q];
            ep[q*4+0]=pv.x; ep[q*4+1]=pv.y; ep[q*4+2]=pv.z; ep[q*4+3]=pv.w;
        }
    }

    float yj[16], lj[16];
    float dd = 0.0f, ee = 0.0f;
    #pragma unroll
    for (int k = 0; k < 16; ++k) {
        yj[k] = es[k] * rt;
        lj[k] = us[k] * rm;
        dd = fmaf(yj[k], lj[k], dd);
        ee += ex2f(lj[k] * LOG2E);
    }
    const float lq = dd - lg2f(ee) * LN2;

    const float4* P4 = reinterpret_cast<const float4*>(lgP);
    float acc = 0.0f;
    #pragma unroll
    for (int i = 0; i < 16; ++i) {
        const float4 r0 = P4[i*4+0], r1 = P4[i*4+1], r2 = P4[i*4+2], r3 = P4[i*4+3];
        float wv =        yj[0]*r0.x;
        wv = fmaf(yj[1],  r0.y, wv); wv = fmaf(yj[2],  r0.z, wv); wv = fmaf(yj[3],  r0.w, wv);
        wv = fmaf(yj[4],  r1.x, wv); wv = fmaf(yj[5],  r1.y, wv); wv = fmaf(yj[6],  r1.z, wv);
        wv = fmaf(yj[7],  r1.w, wv); wv = fmaf(yj[8],  r2.x, wv); wv = fmaf(yj[9],  r2.y, wv);
        wv = fmaf(yj[10], r2.z, wv); wv = fmaf(yj[11], r2.w, wv); wv = fmaf(yj[12], r3.x, wv);
        wv = fmaf(yj[13], r3.y, wv); wv = fmaf(yj[14], r3.z, wv); wv = fmaf(yj[15], r3.w, wv);
        acc = fmaf(ep[i] * rm, wv, acc);
    }
    const float lp = (t == 0) ? -2.7725887222397811f : acc;   // -log(16) at t=0

    outLq[bt] = lq;
    outLp[bt] = lp;
}

extern "C" void kernel_launch(void* const* d_in, const int* in_sizes, int n_in,
                              void* d_out, int out_size)
{
    const float *logits = nullptr, *gum = nullptr, *A = nullptr, *Bm = nullptr,
                *Cm = nullptr, *tP = nullptr;
    for (int i = 0; i < n_in; ++i) {
        switch (in_sizes[i]) {
            case 33554432: logits = (const float*)d_in[i]; break;  // (128,1024,16,16)
            case 2097152:  gum    = (const float*)d_in[i]; break;  // (128,1024,16)
            case 4096:     A      = (const float*)d_in[i]; break;  // (16,16,16)
            case 2048:     Bm     = (const float*)d_in[i]; break;  // (16,16,8)
            case 8192:     Cm     = (const float*)d_in[i]; break;  // (16,32,16)
            case 256:      tP     = (const float*)d_in[i]; break;  // (16,16)
        }
    }
    (void)out_size;
    float* outp = (float*)d_out;
    scan_kernel<<<128, 64>>>(logits, gum);
    expand_kernel<<<dim3(16, 128), 384>>>(A, Bm, outp);
    scalars_kernel<<<dim3(8, 128), 128>>>(tP, Cm, outp);
}

// round 9
// speedup vs baseline: 1.3167x; 1.3167x over previous
#include <cuda_runtime.h>
#include <stdint.h>
#include <math.h>

#define FMASK 0xffffffffu

static __device__ __forceinline__ float ex2f(float x){ float y; asm("ex2.approx.f32 %0, %1;" : "=f"(y) : "f"(x)); return y; }
static __device__ __forceinline__ float lg2f(float x){ float y; asm("lg2.approx.f32 %0, %1;" : "=f"(y) : "f"(x)); return y; }
static __device__ __forceinline__ float rcpf(float x){ float y; asm("rcp.approx.f32 %0, %1;" : "=f"(y) : "f"(x)); return y; }
static __device__ __forceinline__ void cp16(uint32_t dst, const void* src){
    asm volatile("cp.async.cg.shared.global [%0], [%1], 16;" :: "r"(dst), "l"(src) : "memory");
}
static __device__ __forceinline__ void cpcommit(){ asm volatile("cp.async.commit_group;" ::: "memory"); }
static __device__ __forceinline__ void cpwait14(){ asm volatile("cp.async.wait_group 14;" ::: "memory"); }

// packed f32x2 helpers (expansion kernel)
static __device__ __forceinline__ unsigned long long dup2(float x){
    unsigned long long r; asm("mov.b64 %0, {%1, %1};" : "=l"(r) : "f"(x)); return r;
}
static __device__ __forceinline__ unsigned long long pk2(float lo, float hi){
    unsigned long long r; asm("mov.b64 %0, {%1, %2};" : "=l"(r) : "f"(lo), "f"(hi)); return r;
}
static __device__ __forceinline__ unsigned long long fma2(unsigned long long a, unsigned long long b, unsigned long long c){
    unsigned long long d; asm("fma.rn.f32x2 %0, %1, %2, %3;" : "=l"(d) : "l"(a), "l"(b), "l"(c)); return d;
}
static __device__ __forceinline__ unsigned long long mul2(unsigned long long a, unsigned long long b){
    unsigned long long d; asm("mul.rn.f32x2 %0, %1, %2;" : "=l"(d) : "l"(a), "l"(b)); return d;
}
static __device__ __forceinline__ float2 unpk2(unsigned long long v){
    float2 f; asm("mov.b64 {%0, %1}, %2;" : "=f"(f.x), "=f"(f.y) : "l"(v)); return f;
}

// Scratch (allocation-free __device__ globals)
__device__ float g_e[128*1024*16];   // unnormalized softmax numerators e_t
__device__ float g_u[128*1024*16];   // raw mixed logits u_t (l_t = u_t * r_{t-1})
__device__ float g_r[128*1024];      // r_t = 1/S_t  (y_t = e_t * r_t)

// ============================================================================
// Kernel 1: scan — 1 warp per CTA, TWO batch rows per warp.
// Lanes 0-15 -> row 2b (rr=0), lanes 16-31 -> row 2b+1 (rr=1); j = lane & 15.
// Ring slot layout (per step): float idx = k*32 + rr*16 + j  (bank = lane, conflict-free).
// ============================================================================
__global__ __launch_bounds__(32, 1)
void scan_kernel(const float* __restrict__ logits,
                 const float* __restrict__ gum)
{
    constexpr int T = 1024;
    constexpr float SCALE = 2.8853900817779268f;   // (1/tau)*log2(e), tau = 0.5

    __shared__ __align__(16) float ring[16*512];   // 16 slots x 2KB (2 rows)
    __shared__ __align__(16) float gring[16*32];   // 16 slots x 2 rows x 16

    const int b0 = blockIdx.x * 2;
    const int lane = threadIdx.x;
    const int rr = lane >> 4;
    const int j = lane & 15;
    const int bsel = (lane & 16) ;                 // shuffle src base for own row

    const float* L0 = logits + (size_t)b0 * ((size_t)T * 256);
    const float* L1 = L0 + (size_t)T * 256;
    const float* g0 = gum + (size_t)b0 * (T * 16);
    const float* g1 = g0 + T * 16;
    float* pe = g_e + ((size_t)(b0 + rr)) * (T * 16);
    float* pu = g_u + ((size_t)(b0 + rr)) * (T * 16);
    float* pr = g_r + ((size_t)(b0 + rr)) * T;

    uint32_t ring_b  = (uint32_t)__cvta_generic_to_shared(ring);
    uint32_t gring_b = (uint32_t)__cvta_generic_to_shared(gring);

    // per-lane cp.async dst offset within slot: chunk c=lane covers floats [4c,4c+4)
    // of a 256-float row-step -> k=c/4, j0=(c%4)*4 -> byte k*128 + (c%4)*16
    const uint32_t dL = (uint32_t)((lane >> 2) * 128 + (lane & 3) * 16);
    const float* gsrc = (lane & 4) ? g1 : g0;      // gumbel source for lanes 0-7

#define PREFETCH(TT)                                                                     \
    {   const int ft = (TT);                                                             \
        if (ft < T) {                                                                    \
            const int s = ft & 15;                                                       \
            uint32_t sb = ring_b + s*2048;                                               \
            const float* p0 = L0 + (size_t)ft*256 + lane*4;                              \
            const float* p1 = L1 + (size_t)ft*256 + lane*4;                              \
            cp16(sb + dL,              p0);                                              \
            cp16(sb + 1024 + dL,       p0 + 128);                                        \
            cp16(sb + 64 + dL,         p1);                                              \
            cp16(sb + 1024 + 64 + dL,  p1 + 128);                                        \
            if (lane < 8) cp16(gring_b + s*128 + lane*16, gsrc + (size_t)ft*16 + (lane&3)*4); \
        }                                                                                \
        cpcommit();                                                                      \
    }

    // prologue: prefetch steps 0..14
    #pragma unroll
    for (int pt = 0; pt < 15; ++pt) PREFETCH(pt)
    cpwait14();            // slot 0 complete
    __syncwarp();

    float Lc[16], ea[16], eb[16];
    #pragma unroll
    for (int k = 0; k < 16; ++k) { Lc[k] = ring[k*32 + lane]; ea[k] = 1.0f; }
    float gC = gring[lane] * SCALE;
    float rC = 0.0625f * SCALE;   // SCALE * r_{-1}  (y0 uniform)

#define SCAN_SUBSTEP(EIN, EOUT, TT)                                                      \
    {                                                                                    \
        PREFETCH((TT) + 15)                                                              \
        float u0 = EIN[0]*Lc[0], u1 = EIN[1]*Lc[1], u2 = EIN[2]*Lc[2], u3 = EIN[3]*Lc[3];\
        _Pragma("unroll")                                                                \
        for (int k = 4; k < 16; k += 4) {                                                \
            u0 = fmaf(EIN[k+0], Lc[k+0], u0);                                            \
            u1 = fmaf(EIN[k+1], Lc[k+1], u1);                                            \
            u2 = fmaf(EIN[k+2], Lc[k+2], u2);                                            \
            u3 = fmaf(EIN[k+3], Lc[k+3], u3);                                            \
        }                                                                                \
        const float u = (u0+u1)+(u2+u3);                                                 \
        const float x = fmaf(u, rC, gC);                                                 \
        const float en = ex2f(x);                                                        \
        _Pragma("unroll")                                                                \
        for (int k = 0; k < 16; ++k) EOUT[k] = __shfl_sync(FMASK, en, bsel + k);         \
        pe[(TT)*16 + j] = en;                                                            \
        pu[(TT)*16 + j] = u;                                                             \
        cpwait14();                                                                      \
        __syncwarp();                                                                    \
        {   const int s1 = ((TT) + 1) & 15;                                              \
            _Pragma("unroll")                                                            \
            for (int k = 0; k < 16; ++k) Lc[k] = ring[s1*512 + k*32 + lane];             \
            gC = gring[s1*32 + lane] * SCALE;                                            \
        }                                                                                \
        const float sA = (EOUT[0]+EOUT[1])+(EOUT[2]+EOUT[3]);                            \
        const float sB = (EOUT[4]+EOUT[5])+(EOUT[6]+EOUT[7]);                            \
        const float sC = (EOUT[8]+EOUT[9])+(EOUT[10]+EOUT[11]);                          \
        const float sD = (EOUT[12]+EOUT[13])+(EOUT[14]+EOUT[15]);                        \
        const float S = (sA+sB)+(sC+sD);                                                 \
        const float r = rcpf(S);                                                         \
        rC = r * SCALE;                                                                  \
        if (j == 0) pr[TT] = r;                                                          \
    }

    for (int t = 0; t < T; t += 2) {
        SCAN_SUBSTEP(ea, eb, t)
        SCAN_SUBSTEP(eb, ea, t + 1)
    }
#undef SCAN_SUBSTEP
#undef PREFETCH
}

// ============================================================================
// Kernel 2: expansion — A_seq = y·A, B_seq = y·Bm. Bandwidth-bound, f32x2 FMA.
// ============================================================================
__global__ __launch_bounds__(384, 1)
void expand_kernel(const float* __restrict__ Amat,
                   const float* __restrict__ Bmat,
                   float* __restrict__ out)
{
    __shared__ __align__(16) float es[64*16];
    __shared__ float rs[64];

    const int b = blockIdx.y;
    const int t0 = blockIdx.x * 64;
    const int tid = threadIdx.x;
    const int tsub = tid / 96;
    const int e96 = tid % 96;

    float* outA = out;                // (B,T,16,16)
    float* outB = out + 33554432u;    // (B,T,16,8)

    unsigned long long M[32];
    const float* Msrc;
    int stride, base;
    if (e96 < 64) { const int i = e96 >> 2, jc = (e96 & 3) * 4; base = i*16 + jc; stride = 256; Msrc = Amat; }
    else          { const int q = e96 - 64; const int i = q >> 1, jc = (q & 1) * 4; base = i*8 + jc; stride = 128; Msrc = Bmat; }
    #pragma unroll
    for (int k = 0; k < 16; ++k) {
        const float4 v = *reinterpret_cast<const float4*>(Msrc + k*stride + base);
        M[2*k]   = pk2(v.x, v.y);
        M[2*k+1] = pk2(v.z, v.w);
    }

    const float* esrc = g_e + ((size_t)b*1024 + t0) * 16;
    if (tid < 256) *reinterpret_cast<float4*>(&es[tid*4]) = *reinterpret_cast<const float4*>(&esrc[tid*4]);
    if (tid >= 320) rs[tid - 320] = g_r[(size_t)b*1024 + t0 + (tid - 320)];
    __syncthreads();

    float* outp = ((e96 < 64) ? outA : outB) + ((size_t)b*1024 + t0) * (size_t)stride + base;

    #pragma unroll 4
    for (int tt = 0; tt < 16; ++tt) {
        const int tl = tt*4 + tsub;
        const float4* ep4 = reinterpret_cast<const float4*>(&es[tl*16]);
        const float4 y0 = ep4[0], y1 = ep4[1], y2 = ep4[2], y3 = ep4[3];
        unsigned long long d[16];
        d[0]=dup2(y0.x); d[1]=dup2(y0.y); d[2]=dup2(y0.z); d[3]=dup2(y0.w);
        d[4]=dup2(y1.x); d[5]=dup2(y1.y); d[6]=dup2(y1.z); d[7]=dup2(y1.w);
        d[8]=dup2(y2.x); d[9]=dup2(y2.y); d[10]=dup2(y2.z); d[11]=dup2(y2.w);
        d[12]=dup2(y3.x); d[13]=dup2(y3.y); d[14]=dup2(y3.z); d[15]=dup2(y3.w);
        unsigned long long a0 = mul2(d[0], M[0]);
        unsigned long long a1 = mul2(d[0], M[1]);
        #pragma unroll
        for (int k = 1; k < 16; ++k) {
            a0 = fma2(d[k], M[2*k],   a0);
            a1 = fma2(d[k], M[2*k+1], a1);
        }
        const unsigned long long rd = dup2(rs[tl]);
        a0 = mul2(a0, rd);
        a1 = mul2(a1, rd);
        const float2 f0 = unpk2(a0), f1 = unpk2(a1);
        *reinterpret_cast<float4*>(outp + (size_t)tl * stride) = make_float4(f0.x, f0.y, f1.x, f1.y);
    }
}

// ============================================================================
// Kernel 3: scalars — lq, lp, C_seq.
// ============================================================================
__global__ __launch_bounds__(128, 1)
void scalars_kernel(const float* __restrict__ transP,
                    const float* __restrict__ Cmat,
                    float* __restrict__ out)
{
    constexpr float LOG2E = 1.4426950408889634f;
    constexpr float LN2   = 0.6931471805599453f;
    __shared__ __align__(16) float lgP[256];

    const int b = blockIdx.y;
    const int tid = threadIdx.x;
    const int t = blockIdx.x * 128 + tid;

    float* outC  = out + 50331648u;   // (B,1,32,16)
    float* outLq = out + 50397184u;   // (B,T)
    float* outLp = out + 50528256u;   // (B,T)

    lgP[tid] = logf(transP[tid]);
    lgP[tid + 128] = logf(transP[tid + 128]);
    if (blockIdx.x == 0) {
        #pragma unroll
        for (int i = tid; i < 512; i += 128) outC[b*512 + i] = Cmat[i];
    }
    __syncthreads();

    const size_t bt = (size_t)b*1024 + t;
    float es[16], us[16], ep[16];
    {
        const float4* e4 = reinterpret_cast<const float4*>(g_e + bt*16);
        const float4* u4 = reinterpret_cast<const float4*>(g_u + bt*16);
        #pragma unroll
        for (int q = 0; q < 4; ++q) {
            const float4 ev = e4[q], uv = u4[q];
            es[q*4+0]=ev.x; es[q*4+1]=ev.y; es[q*4+2]=ev.z; es[q*4+3]=ev.w;
            us[q*4+0]=uv.x; us[q*4+1]=uv.y; us[q*4+2]=uv.z; us[q*4+3]=uv.w;
        }
    }
    const float rt = g_r[bt];
    float rm;
    if (t == 0) {
        rm = 0.0625f;
        #pragma unroll
        for (int k = 0; k < 16; ++k) ep[k] = 1.0f;
    } else {
        rm = g_r[bt - 1];
        const float4* p4 = reinterpret_cast<const float4*>(g_e + (bt - 1)*16);
        #pragma unroll
        for (int q = 0; q < 4; ++q) {
            const float4 pv = p4[q];
            ep[q*4+0]=pv.x; ep[q*4+1]=pv.y; ep[q*4+2]=pv.z; ep[q*4+3]=pv.w;
        }
    }

    float yj[16], lj[16];
    float dd = 0.0f, ee = 0.0f;
    #pragma unroll
    for (int k = 0; k < 16; ++k) {
        yj[k] = es[k] * rt;
        lj[k] = us[k] * rm;
        dd = fmaf(yj[k], lj[k], dd);
        ee += ex2f(lj[k] * LOG2E);
    }
    const float lq = dd - lg2f(ee) * LN2;

    const float4* P4 = reinterpret_cast<const float4*>(lgP);
    float acc = 0.0f;
    #pragma unroll
    for (int i = 0; i < 16; ++i) {
        const float4 r0 = P4[i*4+0], r1 = P4[i*4+1], r2 = P4[i*4+2], r3 = P4[i*4+3];
        float wv =        yj[0]*r0.x;
        wv = fmaf(yj[1],  r0.y, wv); wv = fmaf(yj[2],  r0.z, wv); wv = fmaf(yj[3],  r0.w, wv);
        wv = fmaf(yj[4],  r1.x, wv); wv = fmaf(yj[5],  r1.y, wv); wv = fmaf(yj[6],  r1.z, wv);
        wv = fmaf(yj[7],  r1.w, wv); wv = fmaf(yj[8],  r2.x, wv); wv = fmaf(yj[9],  r2.y, wv);
        wv = fmaf(yj[10], r2.z, wv); wv = fmaf(yj[11], r2.w, wv); wv = fmaf(yj[12], r3.x, wv);
        wv = fmaf(yj[13], r3.y, wv); wv = fmaf(yj[14], r3.z, wv); wv = fmaf(yj[15], r3.w, wv);
        acc = fmaf(ep[i] * rm, wv, acc);
    }
    const float lp = (t == 0) ? -2.7725887222397811f : acc;   // -log(16) at t=0

    outLq[bt] = lq;
    outLp[bt] = lp;
}

extern "C" void kernel_launch(void* const* d_in, const int* in_sizes, int n_in,
                              void* d_out, int out_size)
{
    const float *logits = nullptr, *gum = nullptr, *A = nullptr, *Bm = nullptr,
                *Cm = nullptr, *tP = nullptr;
    for (int i = 0; i < n_in; ++i) {
        switch (in_sizes[i]) {
            case 33554432: logits = (const float*)d_in[i]; break;  // (128,1024,16,16)
            case 2097152:  gum    = (const float*)d_in[i]; break;  // (128,1024,16)
            case 4096:     A      = (const float*)d_in[i]; break;  // (16,16,16)
            case 2048:     Bm     = (const float*)d_in[i]; break;  // (16,16,8)
            case 8192:     Cm     = (const float*)d_in[i]; break;  // (16,32,16)
            case 256:      tP     = (const float*)d_in[i]; break;  // (16,16)
        }
    }
    (void)out_size;
    float* outp = (float*)d_out;
    scan_kernel<<<64, 32>>>(logits, gum);
    expand_kernel<<<dim3(16, 128), 384>>>(A, Bm, outp);
    scalars_kernel<<<dim3(8, 128), 128>>>(tP, Cm, outp);
}

// round 10
// speedup vs baseline: 1.3836x; 1.0508x over previous
#include <cuda_runtime.h>
#include <stdint.h>
#include <math.h>

#define FMASK 0xffffffffu

static __device__ __forceinline__ float ex2f(float x){ float y; asm("ex2.approx.f32 %0, %1;" : "=f"(y) : "f"(x)); return y; }
static __device__ __forceinline__ float lg2f(float x){ float y; asm("lg2.approx.f32 %0, %1;" : "=f"(y) : "f"(x)); return y; }
static __device__ __forceinline__ float rcpf(float x){ float y; asm("rcp.approx.f32 %0, %1;" : "=f"(y) : "f"(x)); return y; }
static __device__ __forceinline__ void cp16(uint32_t dst, const void* src){
    asm volatile("cp.async.cg.shared.global [%0], [%1], 16;" :: "r"(dst), "l"(src) : "memory");
}
static __device__ __forceinline__ void cpcommit(){ asm volatile("cp.async.commit_group;" ::: "memory"); }
static __device__ __forceinline__ void cpwait14(){ asm volatile("cp.async.wait_group 14;" ::: "memory"); }

// packed f32x2 helpers
union F2 { unsigned long long u; float f[2]; };
static __device__ __forceinline__ unsigned long long dup2(float x){
    unsigned long long r; asm("mov.b64 %0, {%1, %1};" : "=l"(r) : "f"(x)); return r;
}
static __device__ __forceinline__ unsigned long long pk2(float lo, float hi){
    unsigned long long r; asm("mov.b64 %0, {%1, %2};" : "=l"(r) : "f"(lo), "f"(hi)); return r;
}
static __device__ __forceinline__ unsigned long long fma2(unsigned long long a, unsigned long long b, unsigned long long c){
    unsigned long long d; asm("fma.rn.f32x2 %0, %1, %2, %3;" : "=l"(d) : "l"(a), "l"(b), "l"(c)); return d;
}
static __device__ __forceinline__ unsigned long long add2(unsigned long long a, unsigned long long b){
    unsigned long long d; asm("add.rn.f32x2 %0, %1, %2;" : "=l"(d) : "l"(a), "l"(b)); return d;
}
static __device__ __forceinline__ unsigned long long mul2(unsigned long long a, unsigned long long b){
    unsigned long long d; asm("mul.rn.f32x2 %0, %1, %2;" : "=l"(d) : "l"(a), "l"(b)); return d;
}
static __device__ __forceinline__ float2 unpk2(unsigned long long v){
    float2 f; asm("mov.b64 {%0, %1}, %2;" : "=f"(f.x), "=f"(f.y) : "l"(v)); return f;
}

// Scratch (allocation-free __device__ globals)
__device__ float g_e[128*1024*16];   // unnormalized softmax numerators e_t
__device__ float g_u[128*1024*16];   // raw mixed logits u_t (l_t = u_t * r_{t-1})
__device__ float g_r[128*1024];      // r_t = 1/S_t  (y_t = e_t * r_t)

// ============================================================================
// Kernel 1: scan — 1 warp per CTA, one batch row. Shuffle-free recurrence:
// e broadcast via smem (STS + 8x LDS.64 broadcast), S-sum fully in-lane.
// ============================================================================
__global__ __launch_bounds__(32, 1)
void scan_kernel(const float* __restrict__ logits,
                 const float* __restrict__ gum)
{
    constexpr int T = 1024;
    constexpr float SCALE = 2.8853900817779268f;   // (1/tau)*log2(e), tau = 0.5

    __shared__ __align__(16) float ring[16*256];   // logits ring, 16 slots (15 ahead)
    __shared__ __align__(16) float gring[16*16];   // gumbel ring
    __shared__ __align__(8)  float ebc[16];        // e broadcast buffer (one step)

    const int b = blockIdx.x;
    const int lane = threadIdx.x;
    const int j = lane & 15;
    const bool wr = (lane < 16);

    const float* Lrow = logits + (size_t)b * ((size_t)T * 256);
    const float* grow = gum    + (size_t)b * ((size_t)T * 16);
    float* pe = g_e + (size_t)b * (T * 16);
    float* pu = g_u + (size_t)b * (T * 16);
    float* pr = g_r + (size_t)b * T;
    uint32_t ring_b  = (uint32_t)__cvta_generic_to_shared(ring);
    uint32_t gring_b = (uint32_t)__cvta_generic_to_shared(gring);

#define PREFETCH(TT)                                                                     \
    {   const int ft = (TT);                                                             \
        if (ft < T) {                                                                    \
            uint32_t sb = ring_b + (ft & 15)*1024 + lane*16;                             \
            const float* gp = Lrow + (size_t)ft*256 + lane*4;                            \
            cp16(sb, gp);                                                                \
            cp16(sb + 512, gp + 128);                                                    \
            if (lane < 4) cp16(gring_b + (ft & 15)*64 + lane*16,                         \
                               grow + (size_t)ft*16 + lane*4);                           \
        }                                                                                \
        cpcommit();                                                                      \
    }

    // prologue: e_{-1} = 1 (uniform y0), prefetch steps 0..14
    if (wr) ebc[j] = 1.0f;
    #pragma unroll
    for (int pt = 0; pt < 15; ++pt) PREFETCH(pt)

    #pragma unroll 2
    for (int t = 0; t < T; ++t) {
        PREFETCH(t + 15)
        cpwait14();
        __syncwarp();                              // ring slot t + ebc(e_{t-1}) visible

        // all 16 e_{t-1} into registers: 8 broadcast LDS.64
        F2 E[8];
        {
            const float2* eb2 = reinterpret_cast<const float2*>(ebc);
            #pragma unroll
            for (int m = 0; m < 8; ++m) { const float2 v = eb2[m]; E[m].f[0] = v.x; E[m].f[1] = v.y; }
        }

        // column j of L_t + gumbel
        const float* rb = ring + (t & 15)*256;
        float Lc[16];
        #pragma unroll
        for (int k = 0; k < 16; ++k) Lc[k] = rb[k*16 + j];
        const float gC = gring[(t & 15)*16 + j] * SCALE;

        // r_{t-1} = 1/sum(e_{t-1}) — in-lane packed tree (no cross-lane ops)
        unsigned long long s0 = add2(E[0].u, E[1].u);
        unsigned long long s1 = add2(E[2].u, E[3].u);
        unsigned long long s2 = add2(E[4].u, E[5].u);
        unsigned long long s3 = add2(E[6].u, E[7].u);
        s0 = add2(s0, s1); s2 = add2(s2, s3); s0 = add2(s0, s2);
        F2 fs; fs.u = s0;
        const float S = fs.f[0] + fs.f[1];
        const float r = rcpf(S);
        const float rC = r * SCALE;
        if (lane == 0 && t) pr[t - 1] = r;

        // u_j = e_{t-1} . L_t[:,j]
        float u0 = E[0].f[0]*Lc[0],  u1 = E[0].f[1]*Lc[1];
        float u2 = E[1].f[0]*Lc[2],  u3 = E[1].f[1]*Lc[3];
        u0 = fmaf(E[2].f[0], Lc[4],  u0); u1 = fmaf(E[2].f[1], Lc[5],  u1);
        u2 = fmaf(E[3].f[0], Lc[6],  u2); u3 = fmaf(E[3].f[1], Lc[7],  u3);
        u0 = fmaf(E[4].f[0], Lc[8],  u0); u1 = fmaf(E[4].f[1], Lc[9],  u1);
        u2 = fmaf(E[5].f[0], Lc[10], u2); u3 = fmaf(E[5].f[1], Lc[11], u3);
        u0 = fmaf(E[6].f[0], Lc[12], u0); u1 = fmaf(E[6].f[1], Lc[13], u1);
        u2 = fmaf(E[7].f[0], Lc[14], u2); u3 = fmaf(E[7].f[1], Lc[15], u3);
        const float u = (u0 + u1) + (u2 + u3);

        const float x = fmaf(u, rC, gC);
        const float en = ex2f(x);

        if (wr) { ebc[j] = en; pe[t*16 + j] = en; pu[t*16 + j] = u; }
    }

    // epilogue: r_{1023}
    __syncwarp();
    if (lane == 0) {
        float S = 0.0f;
        #pragma unroll
        for (int k = 0; k < 16; ++k) S += ebc[k];
        pr[T - 1] = rcpf(S);
    }
#undef PREFETCH
}

// ============================================================================
// Kernel 2: expansion — A_seq = y·A, B_seq = y·Bm. Bandwidth-bound, f32x2 FMA.
// ============================================================================
__global__ __launch_bounds__(384, 1)
void expand_kernel(const float* __restrict__ Amat,
                   const float* __restrict__ Bmat,
                   float* __restrict__ out)
{
    __shared__ __align__(16) float es[64*16];
    __shared__ float rs[64];

    const int b = blockIdx.y;
    const int t0 = blockIdx.x * 64;
    const int tid = threadIdx.x;
    const int tsub = tid / 96;
    const int e96 = tid % 96;

    float* outA = out;                // (B,T,16,16)
    float* outB = out + 33554432u;    // (B,T,16,8)

    unsigned long long M[32];
    const float* Msrc;
    int stride, base;
    if (e96 < 64) { const int i = e96 >> 2, jc = (e96 & 3) * 4; base = i*16 + jc; stride = 256; Msrc = Amat; }
    else          { const int q = e96 - 64; const int i = q >> 1, jc = (q & 1) * 4; base = i*8 + jc; stride = 128; Msrc = Bmat; }
    #pragma unroll
    for (int k = 0; k < 16; ++k) {
        const float4 v = *reinterpret_cast<const float4*>(Msrc + k*stride + base);
        M[2*k]   = pk2(v.x, v.y);
        M[2*k+1] = pk2(v.z, v.w);
    }

    const float* esrc = g_e + ((size_t)b*1024 + t0) * 16;
    if (tid < 256) *reinterpret_cast<float4*>(&es[tid*4]) = *reinterpret_cast<const float4*>(&esrc[tid*4]);
    if (tid >= 320) rs[tid - 320] = g_r[(size_t)b*1024 + t0 + (tid - 320)];
    __syncthreads();

    float* outp = ((e96 < 64) ? outA : outB) + ((size_t)b*1024 + t0) * (size_t)stride + base;

    #pragma unroll 4
    for (int tt = 0; tt < 16; ++tt) {
        const int tl = tt*4 + tsub;
        const float4* ep4 = reinterpret_cast<const float4*>(&es[tl*16]);
        const float4 y0 = ep4[0], y1 = ep4[1], y2 = ep4[2], y3 = ep4[3];
        unsigned long long d[16];
        d[0]=dup2(y0.x); d[1]=dup2(y0.y); d[2]=dup2(y0.z); d[3]=dup2(y0.w);
        d[4]=dup2(y1.x); d[5]=dup2(y1.y); d[6]=dup2(y1.z); d[7]=dup2(y1.w);
        d[8]=dup2(y2.x); d[9]=dup2(y2.y); d[10]=dup2(y2.z); d[11]=dup2(y2.w);
        d[12]=dup2(y3.x); d[13]=dup2(y3.y); d[14]=dup2(y3.z); d[15]=dup2(y3.w);
        unsigned long long a0 = mul2(d[0], M[0]);
        unsigned long long a1 = mul2(d[0], M[1]);
        #pragma unroll
        for (int k = 1; k < 16; ++k) {
            a0 = fma2(d[k], M[2*k],   a0);
            a1 = fma2(d[k], M[2*k+1], a1);
        }
        const unsigned long long rd = dup2(rs[tl]);
        a0 = mul2(a0, rd);
        a1 = mul2(a1, rd);
        const float2 f0 = unpk2(a0), f1 = unpk2(a1);
        *reinterpret_cast<float4*>(outp + (size_t)tl * stride) = make_float4(f0.x, f0.y, f1.x, f1.y);
    }
}

// ============================================================================
// Kernel 3: scalars — lq, lp, C_seq.
// ============================================================================
__global__ __launch_bounds__(128, 1)
void scalars_kernel(const float* __restrict__ transP,
                    const float* __restrict__ Cmat,
                    float* __restrict__ out)
{
    constexpr float LOG2E = 1.4426950408889634f;
    constexpr float LN2   = 0.6931471805599453f;
    __shared__ __align__(16) float lgP[256];

    const int b = blockIdx.y;
    const int tid = threadIdx.x;
    const int t = blockIdx.x * 128 + tid;

    float* outC  = out + 50331648u;   // (B,1,32,16)
    float* outLq = out + 50397184u;   // (B,T)
    float* outLp = out + 50528256u;   // (B,T)

    lgP[tid] = logf(transP[tid]);
    lgP[tid + 128] = logf(transP[tid + 128]);
    if (blockIdx.x == 0) {
        #pragma unroll
        for (int i = tid; i < 512; i += 128) outC[b*512 + i] = Cmat[i];
    }
    __syncthreads();

    const size_t bt = (size_t)b*1024 + t;
    float es[16], us[16], ep[16];
    {
        const float4* e4 = reinterpret_cast<const float4*>(g_e + bt*16);
        const float4* u4 = reinterpret_cast<const float4*>(g_u + bt*16);
        #pragma unroll
        for (int q = 0; q < 4; ++q) {
            const float4 ev = e4[q], uv = u4[q];
            es[q*4+0]=ev.x; es[q*4+1]=ev.y; es[q*4+2]=ev.z; es[q*4+3]=ev.w;
            us[q*4+0]=uv.x; us[q*4+1]=uv.y; us[q*4+2]=uv.z; us[q*4+3]=uv.w;
        }
    }
    const float rt = g_r[bt];
    float rm;
    if (t == 0) {
        rm = 0.0625f;
        #pragma unroll
        for (int k = 0; k < 16; ++k) ep[k] = 1.0f;
    } else {
        rm = g_r[bt - 1];
        const float4* p4 = reinterpret_cast<const float4*>(g_e + (bt - 1)*16);
        #pragma unroll
        for (int q = 0; q < 4; ++q) {
            const float4 pv = p4[q];
            ep[q*4+0]=pv.x; ep[q*4+1]=pv.y; ep[q*4+2]=pv.z; ep[q*4+3]=pv.w;
        }
    }

    float yj[16], lj[16];
    float dd = 0.0f, ee = 0.0f;
    #pragma unroll
    for (int k = 0; k < 16; ++k) {
        yj[k] = es[k] * rt;
        lj[k] = us[k] * rm;
        dd = fmaf(yj[k], lj[k], dd);
        ee += ex2f(lj[k] * LOG2E);
    }
    const float lq = dd - lg2f(ee) * LN2;

    const float4* P4 = reinterpret_cast<const float4*>(lgP);
    float acc = 0.0f;
    #pragma unroll
    for (int i = 0; i < 16; ++i) {
        const float4 r0 = P4[i*4+0], r1 = P4[i*4+1], r2 = P4[i*4+2], r3 = P4[i*4+3];
        float wv =        yj[0]*r0.x;
        wv = fmaf(yj[1],  r0.y, wv); wv = fmaf(yj[2],  r0.z, wv); wv = fmaf(yj[3],  r0.w, wv);
        wv = fmaf(yj[4],  r1.x, wv); wv = fmaf(yj[5],  r1.y, wv); wv = fmaf(yj[6],  r1.z, wv);
        wv = fmaf(yj[7],  r1.w, wv); wv = fmaf(yj[8],  r2.x, wv); wv = fmaf(yj[9],  r2.y, wv);
        wv = fmaf(yj[10], r2.z, wv); wv = fmaf(yj[11], r2.w, wv); wv = fmaf(yj[12], r3.x, wv);
        wv = fmaf(yj[13], r3.y, wv); wv = fmaf(yj[14], r3.z, wv); wv = fmaf(yj[15], r3.w, wv);
        acc = fmaf(ep[i] * rm, wv, acc);
    }
    const float lp = (t == 0) ? -2.7725887222397811f : acc;   // -log(16) at t=0

    outLq[bt] = lq;
    outLp[bt] = lp;
}

extern "C" void kernel_launch(void* const* d_in, const int* in_sizes, int n_in,
                              void* d_out, int out_size)
{
    const float *logits = nullptr, *gum = nullptr, *A = nullptr, *Bm = nullptr,
                *Cm = nullptr, *tP = nullptr;
    for (int i = 0; i < n_in; ++i) {
        switch (in_sizes[i]) {
            case 33554432: logits = (const float*)d_in[i]; break;  // (128,1024,16,16)
            case 2097152:  gum    = (const float*)d_in[i]; break;  // (128,1024,16)
            case 4096:     A      = (const float*)d_in[i]; break;  // (16,16,16)
            case 2048:     Bm     = (const float*)d_in[i]; break;  // (16,16,8)
            case 8192:     Cm     = (const float*)d_in[i]; break;  // (16,32,16)
            case 256:      tP     = (const float*)d_in[i]; break;  // (16,16)
        }
    }
    (void)out_size;
    float* outp = (float*)d_out;
    scan_kernel<<<128, 32>>>(logits, gum);
    expand_kernel<<<dim3(16, 128), 384>>>(A, Bm, outp);
    scalars_kernel<<<dim3(8, 128), 128>>>(tP, Cm, outp);
}

// round 13
// speedup vs baseline: 1.7745x; 1.2825x over previous
#include <cuda_runtime.h>
#include <stdint.h>
#include <math.h>

#define FMASK 0xffffffffu

static __device__ __forceinline__ float ex2f(float x){ float y; asm("ex2.approx.f32 %0, %1;" : "=f"(y) : "f"(x)); return y; }
static __device__ __forceinline__ float lg2f(float x){ float y; asm("lg2.approx.f32 %0, %1;" : "=f"(y) : "f"(x)); return y; }
static __device__ __forceinline__ float rcpf(float x){ float y; asm("rcp.approx.f32 %0, %1;" : "=f"(y) : "f"(x)); return y; }
static __device__ __forceinline__ void cp16(uint32_t dst, const void* src){
    asm volatile("cp.async.cg.shared.global [%0], [%1], 16;" :: "r"(dst), "l"(src) : "memory");
}
static __device__ __forceinline__ void cpcommit(){ asm volatile("cp.async.commit_group;" ::: "memory"); }
static __device__ __forceinline__ void cpwait14(){ asm volatile("cp.async.wait_group 14;" ::: "memory"); }

// packed f32x2 helpers
union F2 { unsigned long long u; float f[2]; };
static __device__ __forceinline__ unsigned long long dup2(float x){
    unsigned long long r; asm("mov.b64 %0, {%1, %1};" : "=l"(r) : "f"(x)); return r;
}
static __device__ __forceinline__ unsigned long long pk2(float lo, float hi){
    unsigned long long r; asm("mov.b64 %0, {%1, %2};" : "=l"(r) : "f"(lo), "f"(hi)); return r;
}
static __device__ __forceinline__ unsigned long long fma2(unsigned long long a, unsigned long long b, unsigned long long c){
    unsigned long long d; asm("fma.rn.f32x2 %0, %1, %2, %3;" : "=l"(d) : "l"(a), "l"(b), "l"(c)); return d;
}
static __device__ __forceinline__ unsigned long long add2(unsigned long long a, unsigned long long b){
    unsigned long long d; asm("add.rn.f32x2 %0, %1, %2;" : "=l"(d) : "l"(a), "l"(b)); return d;
}
static __device__ __forceinline__ unsigned long long mul2(unsigned long long a, unsigned long long b){
    unsigned long long d; asm("mul.rn.f32x2 %0, %1, %2;" : "=l"(d) : "l"(a), "l"(b)); return d;
}
static __device__ __forceinline__ float2 unpk2(unsigned long long v){
    float2 f; asm("mov.b64 {%0, %1}, %2;" : "=f"(f.x), "=f"(f.y) : "l"(v)); return f;
}

// Scratch (allocation-free __device__ globals)
__device__ float g_e[128*1024*16];   // unnormalized softmax numerators e_t
__device__ float g_u[128*1024*16];   // raw mixed logits u_t (l_t = u_t * r_{t-1})
__device__ float g_r[128*1024];      // r_t = 1/S_t  (y_t = e_t * r_t)

// ============================================================================
// Kernel 1: scan — 1 warp per CTA, one batch row. BRANCH-FREE hot loop:
// no if{} blocks (ptxas BSSY/BSYNC envelopes cost ~70 cyc each per step).
// e broadcast via smem STS + 8x LDS.64; S-sum fully in-lane.
// ============================================================================
__global__ __launch_bounds__(32, 1)
void scan_kernel(const float* __restrict__ logits,
                 const float* __restrict__ gum)
{
    constexpr int T = 1024;
    constexpr float SCALE = 2.8853900817779268f;   // (1/tau)*log2(e), tau = 0.5

    __shared__ __align__(16) float ring[16*256];   // logits ring, 16 slots (15 ahead)
    __shared__ __align__(16) float gring[16*16];   // gumbel ring
    __shared__ __align__(8)  float ebc[16];        // e broadcast buffer (one step)

    const int b = blockIdx.x;
    const int lane = threadIdx.x;
    const int j = lane & 15;

    const float* Lrow = logits + (size_t)b * ((size_t)T * 256);
    const float* grow = gum    + (size_t)b * ((size_t)T * 16);
    float* pe = g_e + (size_t)b * (T * 16) + j;
    float* pu = g_u + (size_t)b * (T * 16) + j;
    float* pr = g_r + (size_t)b * T;
    uint32_t ring_b  = (uint32_t)__cvta_generic_to_shared(ring);
    uint32_t gring_b = (uint32_t)__cvta_generic_to_shared(gring);

    // prologue: e_{-1} = 1 (uniform y0); prefetch steps 0..14 (one group each)
    ebc[j] = 1.0f;                                  // all lanes, dup writes collapse
    #pragma unroll
    for (int pt = 0; pt < 15; ++pt) {
        uint32_t sb = ring_b + pt*1024 + lane*16;
        const float* gp = Lrow + (size_t)pt*256 + lane*4;
        cp16(sb, gp);
        cp16(sb + 512, gp + 128);
        if (lane < 4) cp16(gring_b + pt*64 + lane*16, grow + (size_t)pt*16 + lane*4);
        cpcommit();
    }

    const float* gq = grow + (size_t)(lane & 3) * 4;   // gumbel source (lanes 0-3 used)

    #pragma unroll 4
    for (int t = 0; t < T; ++t) {
        // ---- branch-free prefetch of step t+15 (clamped source, safe slot) ----
        {
            const int ft = (t + 15 < T) ? (t + 15) : (T - 1);     // SEL, no branch
            uint32_t sb = ring_b + ((t + 15) & 15)*1024 + lane*16;
            const float* gp = Lrow + (size_t)ft*256 + lane*4;
            cp16(sb, gp);
            cp16(sb + 512, gp + 128);
            if (lane < 4) cp16(gring_b + ((t + 15) & 15)*64 + lane*16, gq + (size_t)ft*16);
            cpcommit();
        }
        cpwait14();
        __syncwarp();                              // ring slot t + ebc(e_{t-1}) visible

        // all 16 e_{t-1} into registers: 8 broadcast LDS.64
        F2 E[8];
        {
            const float2* eb2 = reinterpret_cast<const float2*>(ebc);
            #pragma unroll
            for (int m = 0; m < 8; ++m) { const float2 v = eb2[m]; E[m].f[0] = v.x; E[m].f[1] = v.y; }
        }

        // column j of L_t + gumbel
        const float* rb = ring + (t & 15)*256;
        float Lc[16];
        #pragma unroll
        for (int k = 0; k < 16; ++k) Lc[k] = rb[k*16 + j];
        const float gC = gring[(t & 15)*16 + j] * SCALE;

        // r_{t-1} = 1/sum(e_{t-1}) — in-lane packed tree
        unsigned long long s0 = add2(E[0].u, E[1].u);
        unsigned long long s1 = add2(E[2].u, E[3].u);
        unsigned long long s2 = add2(E[4].u, E[5].u);
        unsigned long long s3 = add2(E[6].u, E[7].u);
        s0 = add2(s0, s1); s2 = add2(s2, s3); s0 = add2(s0, s2);
        F2 fs; fs.u = s0;
        const float S = fs.f[0] + fs.f[1];
        const float r = rcpf(S);
        const float rC = r * SCALE;
        // pr[t-1] = r ; at t=0 writes a bogus value to pr[0], overwritten at t=1 (in-order)
        const int tprev = (t > 0) ? (t - 1) : 0;   // SEL
        if (lane == 0) pr[tprev] = r;              // single predicated STG

        // u_j = e_{t-1} . L_t[:,j]
        float u0 = E[0].f[0]*Lc[0],  u1 = E[0].f[1]*Lc[1];
        float u2 = E[1].f[0]*Lc[2],  u3 = E[1].f[1]*Lc[3];
        u0 = fmaf(E[2].f[0], Lc[4],  u0); u1 = fmaf(E[2].f[1], Lc[5],  u1);
        u2 = fmaf(E[3].f[0], Lc[6],  u2); u3 = fmaf(E[3].f[1], Lc[7],  u3);
        u0 = fmaf(E[4].f[0], Lc[8],  u0); u1 = fmaf(E[4].f[1], Lc[9],  u1);
        u2 = fmaf(E[5].f[0], Lc[10], u2); u3 = fmaf(E[5].f[1], Lc[11], u3);
        u0 = fmaf(E[6].f[0], Lc[12], u0); u1 = fmaf(E[6].f[1], Lc[13], u1);
        u2 = fmaf(E[7].f[0], Lc[14], u2); u3 = fmaf(E[7].f[1], Lc[15], u3);
        const float u = (u0 + u1) + (u2 + u3);

        const float x = fmaf(u, rC, gC);
        const float en = ex2f(x);

        // all-lane stores (lane pairs duplicate -> write-collapse / coalesce; no branch)
        ebc[j] = en;
        pe[(size_t)t*16] = en;
        pu[(size_t)t*16] = u;
    }

    // epilogue: r_{1023}
    __syncwarp();
    if (lane == 0) {
        float S = 0.0f;
        #pragma unroll
        for (int k = 0; k < 16; ++k) S += ebc[k];
        pr[T - 1] = rcpf(S);
    }
}

// ============================================================================
// Kernel 2: expansion — A_seq = y·A, B_seq = y·Bm. Bandwidth-bound, f32x2 FMA.
// ============================================================================
__global__ __launch_bounds__(384, 1)
void expand_kernel(const float* __restrict__ Amat,
                   const float* __restrict__ Bmat,
                   float* __restrict__ out)
{
    __shared__ __align__(16) float es[64*16];
    __shared__ float rs[64];

    const int b = blockIdx.y;
    const int t0 = blockIdx.x * 64;
    const int tid = threadIdx.x;
    const int tsub = tid / 96;
    const int e96 = tid % 96;

    float* outA = out;                // (B,T,16,16)
    float* outB = out + 33554432u;    // (B,T,16,8)

    unsigned long long M[32];
    const float* Msrc;
    int stride, base;
    if (e96 < 64) { const int i = e96 >> 2, jc = (e96 & 3) * 4; base = i*16 + jc; stride = 256; Msrc = Amat; }
    else          { const int q = e96 - 64; const int i = q >> 1, jc = (q & 1) * 4; base = i*8 + jc; stride = 128; Msrc = Bmat; }
    #pragma unroll
    for (int k = 0; k < 16; ++k) {
        const float4 v = *reinterpret_cast<const float4*>(Msrc + k*stride + base);
        M[2*k]   = pk2(v.x, v.y);
        M[2*k+1] = pk2(v.z, v.w);
    }

    const float* esrc = g_e + ((size_t)b*1024 + t0) * 16;
    if (tid < 256) *reinterpret_cast<float4*>(&es[tid*4]) = *reinterpret_cast<const float4*>(&esrc[tid*4]);
    if (tid >= 320) rs[tid - 320] = g_r[(size_t)b*1024 + t0 + (tid - 320)];
    __syncthreads();

    float* outp = ((e96 < 64) ? outA : outB) + ((size_t)b*1024 + t0) * (size_t)stride + base;

    #pragma unroll 4
    for (int tt = 0; tt < 16; ++tt) {
        const int tl = tt*4 + tsub;
        const float4* ep4 = reinterpret_cast<const float4*>(&es[tl*16]);
        const float4 y0 = ep4[0], y1 = ep4[1], y2 = ep4[2], y3 = ep4[3];
        unsigned long long d[16];
        d[0]=dup2(y0.x); d[1]=dup2(y0.y); d[2]=dup2(y0.z); d[3]=dup2(y0.w);
        d[4]=dup2(y1.x); d[5]=dup2(y1.y); d[6]=dup2(y1.z); d[7]=dup2(y1.w);
        d[8]=dup2(y2.x); d[9]=dup2(y2.y); d[10]=dup2(y2.z); d[11]=dup2(y2.w);
        d[12]=dup2(y3.x); d[13]=dup2(y3.y); d[14]=dup2(y3.z); d[15]=dup2(y3.w);
        unsigned long long a0 = mul2(d[0], M[0]);
        unsigned long long a1 = mul2(d[0], M[1]);
        #pragma unroll
        for (int k = 1; k < 16; ++k) {
            a0 = fma2(d[k], M[2*k],   a0);
            a1 = fma2(d[k], M[2*k+1], a1);
        }
        const unsigned long long rd = dup2(rs[tl]);
        a0 = mul2(a0, rd);
        a1 = mul2(a1, rd);
        const float2 f0 = unpk2(a0), f1 = unpk2(a1);
        *reinterpret_cast<float4*>(outp + (size_t)tl * stride) = make_float4(f0.x, f0.y, f1.x, f1.y);
    }
}

// ============================================================================
// Kernel 3: scalars — lq, lp, C_seq.
// ============================================================================
__global__ __launch_bounds__(128, 1)
void scalars_kernel(const float* __restrict__ transP,
                    const float* __restrict__ Cmat,
                    float* __restrict__ out)
{
    constexpr float LOG2E = 1.4426950408889634f;
    constexpr float LN2   = 0.6931471805599453f;
    __shared__ __align__(16) float lgP[256];

    const int b = blockIdx.y;
    const int tid = threadIdx.x;
    const int t = blockIdx.x * 128 + tid;

    float* outC  = out + 50331648u;   // (B,1,32,16)
    float* outLq = out + 50397184u;   // (B,T)
    float* outLp = out + 50528256u;   // (B,T)

    lgP[tid] = logf(transP[tid]);
    lgP[tid + 128] = logf(transP[tid + 128]);
    if (blockIdx.x == 0) {
        #pragma unroll
        for (int i = tid; i < 512; i += 128) outC[b*512 + i] = Cmat[i];
    }
    __syncthreads();

    const size_t bt = (size_t)b*1024 + t;
    float es[16], us[16], ep[16];
    {
        const float4* e4 = reinterpret_cast<const float4*>(g_e + bt*16);
        const float4* u4 = reinterpret_cast<const float4*>(g_u + bt*16);
        #pragma unroll
        for (int q = 0; q < 4; ++q) {
            const float4 ev = e4[q], uv = u4[q];
            es[q*4+0]=ev.x; es[q*4+1]=ev.y; es[q*4+2]=ev.z; es[q*4+3]=ev.w;
            us[q*4+0]=uv.x; us[q*4+1]=uv.y; us[q*4+2]=uv.z; us[q*4+3]=uv.w;
        }
    }
    const float rt = g_r[bt];
    float rm;
    if (t == 0) {
        rm = 0.0625f;
        #pragma unroll
        for (int k = 0; k < 16; ++k) ep[k] = 1.0f;
    } else {
        rm = g_r[bt - 1];
        const float4* p4 = reinterpret_cast<const float4*>(g_e + (bt - 1)*16);
        #pragma unroll
        for (int q = 0; q < 4; ++q) {
            const float4 pv = p4[q];
            ep[q*4+0]=pv.x; ep[q*4+1]=pv.y; ep[q*4+2]=pv.z; ep[q*4+3]=pv.w;
        }
    }

    float yj[16], lj[16];
    float dd = 0.0f, ee = 0.0f;
    #pragma unroll
    for (int k = 0; k < 16; ++k) {
        yj[k] = es[k] * rt;
        lj[k] = us[k] * rm;
        dd = fmaf(yj[k], lj[k], dd);
        ee += ex2f(lj[k] * LOG2E);
    }
    const float lq = dd - lg2f(ee) * LN2;

    const float4* P4 = reinterpret_cast<const float4*>(lgP);
    float acc = 0.0f;
    #pragma unroll
    for (int i = 0; i < 16; ++i) {
        const float4 r0 = P4[i*4+0], r1 = P4[i*4+1], r2 = P4[i*4+2], r3 = P4[i*4+3];
        float wv =        yj[0]*r0.x;
        wv = fmaf(yj[1],  r0.y, wv); wv = fmaf(yj[2],  r0.z, wv); wv = fmaf(yj[3],  r0.w, wv);
        wv = fmaf(yj[4],  r1.x, wv); wv = fmaf(yj[5],  r1.y, wv); wv = fmaf(yj[6],  r1.z, wv);
        wv = fmaf(yj[7],  r1.w, wv); wv = fmaf(yj[8],  r2.x, wv); wv = fmaf(yj[9],  r2.y, wv);
        wv = fmaf(yj[10], r2.z, wv); wv = fmaf(yj[11], r2.w, wv); wv = fmaf(yj[12], r3.x, wv);
        wv = fmaf(yj[13], r3.y, wv); wv = fmaf(yj[14], r3.z, wv); wv = fmaf(yj[15], r3.w, wv);
        acc = fmaf(ep[i] * rm, wv, acc);
    }
    const float lp = (t == 0) ? -2.7725887222397811f : acc;   // -log(16) at t=0

    outLq[bt] = lq;
    outLp[bt] = lp;
}

extern "C" void kernel_launch(void* const* d_in, const int* in_sizes, int n_in,
                              void* d_out, int out_size)
{
    const float *logits = nullptr, *gum = nullptr, *A = nullptr, *Bm = nullptr,
                *Cm = nullptr, *tP = nullptr;
    for (int i = 0; i < n_in; ++i) {
        switch (in_sizes[i]) {
            case 33554432: logits = (const float*)d_in[i]; break;  // (128,1024,16,16)
            case 2097152:  gum    = (const float*)d_in[i]; break;  // (128,1024,16)
            case 4096:     A      = (const float*)d_in[i]; break;  // (16,16,16)
            case 2048:     Bm     = (const float*)d_in[i]; break;  // (16,16,8)
            case 8192:     Cm     = (const float*)d_in[i]; break;  // (16,32,16)
            case 256:      tP     = (const float*)d_in[i]; break;  // (16,16)
        }
    }
    (void)out_size;
    float* outp = (float*)d_out;
    scan_kernel<<<128, 32>>>(logits, gum);
    expand_kernel<<<dim3(16, 128), 384>>>(A, Bm, outp);
    scalars_kernel<<<dim3(8, 128), 128>>>(tP, Cm, outp);
}